// round 1
// baseline (speedup 1.0000x reference)
#include <cuda_runtime.h>

// Problem constants
#define BSZ     8
#define KDIM    4096
#define NDIM    11008
#define RPW     4                       // rows per warp task
#define SPLITK  2
#define KCH     (KDIM / SPLITK)         // 2048 floats per K-chunk
#define KITERS  (KCH / 128)             // 16 iterations (warp covers 128 floats/iter)
#define WARPS_PER_CTA 8
#define THREADS (WARPS_PER_CTA * 32)
#define NCTAS   148
#define TOTAL_WARPS (NCTAS * WARPS_PER_CTA)   // 1184
#define NROWGROUPS (NDIM / RPW)               // 2752
#define NTASKS  (NROWGROUPS * SPLITK)         // 5504
#define SMEM_BYTES (BSZ * KDIM * 4)           // 131072

// Split-K partial sums: [SPLITK][BSZ][NDIM]
__device__ float g_partial[SPLITK * BSZ * NDIM];

// ---- packed f32x2 helpers (Blackwell f32x2 pipe) ----
__device__ __forceinline__ unsigned long long pk2(float lo, float hi) {
    unsigned long long r;
    asm("mov.b64 %0, {%1, %2};" : "=l"(r) : "f"(lo), "f"(hi));
    return r;
}
__device__ __forceinline__ void ffma2(unsigned long long& d,
                                      unsigned long long a,
                                      unsigned long long b) {
    asm("fma.rn.f32x2 %0, %1, %2, %0;" : "+l"(d) : "l"(a), "l"(b));
}
__device__ __forceinline__ float sum2(unsigned long long a) {
    float lo, hi;
    asm("mov.b64 {%0, %1}, %2;" : "=f"(lo), "=f"(hi) : "l"(a));
    return lo + hi;
}

extern __shared__ float xs[];   // [BSZ][KDIM] staged activations

__global__ __launch_bounds__(THREADS, 1)
void asl_gemv_kernel(const float* __restrict__ x,
                     const float* __restrict__ w) {
    // ---- stage x into shared memory (131 KB), once per CTA ----
    {
        const float4* x4  = reinterpret_cast<const float4*>(x);
        float4*       xs4 = reinterpret_cast<float4*>(xs);
        #pragma unroll 4
        for (int i = threadIdx.x; i < BSZ * KDIM / 4; i += THREADS)
            xs4[i] = x4[i];
    }
    __syncthreads();

    const int lane  = threadIdx.x & 31;
    const int gwarp = blockIdx.x * WARPS_PER_CTA + (threadIdx.x >> 5);
    const float4* xs4 = reinterpret_cast<const float4*>(xs);

    for (int task = gwarp; task < NTASKS; task += TOTAL_WARPS) {
        const int rg    = task >> 1;        // row group
        const int kc    = task & 1;         // K-chunk
        const int n0    = rg * RPW;
        const int kbase = kc * KCH;         // float offset into K

        // weight row base pointers (float4 units); row stride = KDIM/4
        const float4* wr = reinterpret_cast<const float4*>(
            w + (size_t)n0 * KDIM + kbase);
        const float4* xb = xs4 + (kbase >> 2);   // x chunk base (float4)

        unsigned long long acc[RPW][BSZ];
        #pragma unroll
        for (int r = 0; r < RPW; r++)
            #pragma unroll
            for (int b = 0; b < BSZ; b++)
                acc[r][b] = 0ULL;

        #pragma unroll 2
        for (int it = 0; it < KITERS; it++) {
            const int koff = it * 32 + lane;     // float4 index within chunk
            float4 w0 = wr[              koff];
            float4 w1 = wr[    (KDIM/4) + koff];
            float4 w2 = wr[2 * (KDIM/4) + koff];
            float4 w3 = wr[3 * (KDIM/4) + koff];

            unsigned long long w0l = pk2(w0.x, w0.y), w0h = pk2(w0.z, w0.w);
            unsigned long long w1l = pk2(w1.x, w1.y), w1h = pk2(w1.z, w1.w);
            unsigned long long w2l = pk2(w2.x, w2.y), w2h = pk2(w2.z, w2.w);
            unsigned long long w3l = pk2(w3.x, w3.y), w3h = pk2(w3.z, w3.w);

            #pragma unroll
            for (int b = 0; b < BSZ; b++) {
                float4 xv = xb[b * (KDIM / 4) + koff];
                unsigned long long xl = pk2(xv.x, xv.y);
                unsigned long long xh = pk2(xv.z, xv.w);
                ffma2(acc[0][b], w0l, xl); ffma2(acc[0][b], w0h, xh);
                ffma2(acc[1][b], w1l, xl); ffma2(acc[1][b], w1h, xh);
                ffma2(acc[2][b], w2l, xl); ffma2(acc[2][b], w2h, xh);
                ffma2(acc[3][b], w3l, xl); ffma2(acc[3][b], w3h, xh);
            }
        }

        // ---- warp reduction: collapse f32x2 -> f32, then 5-step shfl_down ----
        float vals[RPW][BSZ];
        #pragma unroll
        for (int r = 0; r < RPW; r++) {
            #pragma unroll
            for (int b = 0; b < BSZ; b++) {
                float s = sum2(acc[r][b]);
                s += __shfl_down_sync(0xFFFFFFFFu, s, 16);
                s += __shfl_down_sync(0xFFFFFFFFu, s, 8);
                s += __shfl_down_sync(0xFFFFFFFFu, s, 4);
                s += __shfl_down_sync(0xFFFFFFFFu, s, 2);
                s += __shfl_down_sync(0xFFFFFFFFu, s, 1);
                vals[r][b] = s;
            }
        }

        if (lane == 0) {
            // partial[kc][b][n0..n0+3] as one float4 per b (coalesced-ish STG.128)
            #pragma unroll
            for (int b = 0; b < BSZ; b++) {
                float4 o;
                o.x = vals[0][b]; o.y = vals[1][b];
                o.z = vals[2][b]; o.w = vals[3][b];
                float* dst = g_partial + ((size_t)kc * BSZ + b) * NDIM + n0;
                *reinterpret_cast<float4*>(dst) = o;
            }
        }
    }
}

// out[b*NDIM+n] = partial[0][b][n] + partial[1][b][n]  (fully coalesced float4)
__global__ void asl_combine_kernel(float* __restrict__ out) {
    const int i = blockIdx.x * blockDim.x + threadIdx.x;   // float4 index
    const int total4 = BSZ * NDIM / 4;                     // 22016
    if (i < total4) {
        const float4* p4 = reinterpret_cast<const float4*>(g_partial);
        float4 a = p4[i];
        float4 b = p4[i + total4];
        float4 o;
        o.x = a.x + b.x; o.y = a.y + b.y;
        o.z = a.z + b.z; o.w = a.w + b.w;
        reinterpret_cast<float4*>(out)[i] = o;
    }
}

extern "C" void kernel_launch(void* const* d_in, const int* in_sizes, int n_in,
                              void* d_out, int out_size) {
    const float* x = (const float*)d_in[0];
    const float* w = (const float*)d_in[1];
    // defensive: if input order is swapped, fix it by size
    if (n_in >= 2 && in_sizes[0] == NDIM * KDIM) {
        const float* t = x; x = w; w = t;
    }
    float* out = (float*)d_out;

    cudaFuncSetAttribute(asl_gemv_kernel,
                         cudaFuncAttributeMaxDynamicSharedMemorySize,
                         SMEM_BYTES);

    asl_gemv_kernel<<<NCTAS, THREADS, SMEM_BYTES>>>(x, w);

    const int total4 = BSZ * NDIM / 4;
    asl_combine_kernel<<<(total4 + 255) / 256, 256>>>(out);
}

// round 2
// speedup vs baseline: 1.2579x; 1.2579x over previous
#include <cuda_runtime.h>

// Problem constants
#define BSZ     8
#define KDIM    4096
#define NDIM    11008
#define RPW     4                       // rows per warp task
#define SPLITK  4
#define KCH     (KDIM / SPLITK)         // 1024 floats per K-chunk
#define KITERS  (KCH / 128)             // 8 iterations (warp covers 128 floats/iter)
#define WARPS_PER_CTA 16
#define THREADS (WARPS_PER_CTA * 32)    // 512
#define NCTAS   148
#define TOTAL_WARPS (NCTAS * WARPS_PER_CTA)   // 2368
#define NROWGROUPS (NDIM / RPW)               // 2752
#define NTASKS  (NROWGROUPS * SPLITK)         // 11008
#define SMEM_BYTES (BSZ * KDIM * 4)           // 131072

// Split-K partial sums: [SPLITK][BSZ][NDIM]
__device__ float g_partial[SPLITK * BSZ * NDIM];

// ---- packed f32x2 FMA (Blackwell f32x2 pipe) ----
__device__ __forceinline__ void ffma2(unsigned long long& d,
                                      unsigned long long a,
                                      unsigned long long b) {
    asm("fma.rn.f32x2 %0, %1, %2, %0;" : "+l"(d) : "l"(a), "l"(b));
}
__device__ __forceinline__ float sum2(unsigned long long a) {
    float lo, hi;
    asm("mov.b64 {%0, %1}, %2;" : "=f"(lo), "=f"(hi) : "l"(a));
    return lo + hi;
}
// streaming 128-bit global load as two packed f32x2 words (bypasses L1 reuse)
__device__ __forceinline__ void ldg_cs_v2u64(const void* p,
                                             unsigned long long& a,
                                             unsigned long long& b) {
    asm("ld.global.cs.v2.u64 {%0, %1}, [%2];"
        : "=l"(a), "=l"(b) : "l"(p));
}

extern __shared__ float xs[];   // [BSZ][KDIM] staged activations

__global__ __launch_bounds__(THREADS, 1)
void asl_gemv_kernel(const float* __restrict__ x,
                     const float* __restrict__ w) {
    // ---- stage x into shared memory (131 KB), once per CTA ----
    {
        const float4* x4  = reinterpret_cast<const float4*>(x);
        float4*       xs4 = reinterpret_cast<float4*>(xs);
        #pragma unroll 4
        for (int i = threadIdx.x; i < BSZ * KDIM / 4; i += THREADS)
            xs4[i] = x4[i];
    }
    __syncthreads();

    const int lane  = threadIdx.x & 31;
    const int gwarp = blockIdx.x * WARPS_PER_CTA + (threadIdx.x >> 5);
    const ulonglong2* xs2 = reinterpret_cast<const ulonglong2*>(xs);

    for (int task = gwarp; task < NTASKS; task += TOTAL_WARPS) {
        const int rg    = task / SPLITK;      // row group
        const int kc    = task % SPLITK;      // K-chunk
        const int n0    = rg * RPW;
        const int kbase = kc * KCH;           // float offset into K

        // weight row base (bytes); row stride = KDIM floats
        const char* wr = reinterpret_cast<const char*>(
            w + (size_t)n0 * KDIM + kbase);
        const ulonglong2* xb = xs2 + (kbase >> 2);  // x chunk base (16B units)

        unsigned long long acc[RPW][BSZ];
        #pragma unroll
        for (int r = 0; r < RPW; r++)
            #pragma unroll
            for (int b = 0; b < BSZ; b++)
                acc[r][b] = 0ULL;

        #pragma unroll 2
        for (int it = 0; it < KITERS; it++) {
            const int koff = (it * 32 + lane) * 16;   // byte offset within chunk

            unsigned long long w0l, w0h, w1l, w1h, w2l, w2h, w3l, w3h;
            ldg_cs_v2u64(wr +                  koff, w0l, w0h);
            ldg_cs_v2u64(wr +     KDIM * 4 +   koff, w1l, w1h);
            ldg_cs_v2u64(wr + 2 * KDIM * 4 +   koff, w2l, w2h);
            ldg_cs_v2u64(wr + 3 * KDIM * 4 +   koff, w3l, w3h);

            const int xoff = it * 32 + lane;          // 16B-unit offset
            #pragma unroll
            for (int b = 0; b < BSZ; b++) {
                ulonglong2 xv = xb[b * (KDIM / 4) + xoff];
                ffma2(acc[0][b], w0l, xv.x); ffma2(acc[0][b], w0h, xv.y);
                ffma2(acc[1][b], w1l, xv.x); ffma2(acc[1][b], w1h, xv.y);
                ffma2(acc[2][b], w2l, xv.x); ffma2(acc[2][b], w2h, xv.y);
                ffma2(acc[3][b], w3l, xv.x); ffma2(acc[3][b], w3h, xv.y);
            }
        }

        // ---- warp reduction: collapse f32x2 -> f32, then 5-step shfl_down ----
        float vals[RPW][BSZ];
        #pragma unroll
        for (int r = 0; r < RPW; r++) {
            #pragma unroll
            for (int b = 0; b < BSZ; b++) {
                float s = sum2(acc[r][b]);
                s += __shfl_down_sync(0xFFFFFFFFu, s, 16);
                s += __shfl_down_sync(0xFFFFFFFFu, s, 8);
                s += __shfl_down_sync(0xFFFFFFFFu, s, 4);
                s += __shfl_down_sync(0xFFFFFFFFu, s, 2);
                s += __shfl_down_sync(0xFFFFFFFFu, s, 1);
                vals[r][b] = s;
            }
        }

        if (lane == 0) {
            #pragma unroll
            for (int b = 0; b < BSZ; b++) {
                float4 o;
                o.x = vals[0][b]; o.y = vals[1][b];
                o.z = vals[2][b]; o.w = vals[3][b];
                float* dst = g_partial + ((size_t)kc * BSZ + b) * NDIM + n0;
                *reinterpret_cast<float4*>(dst) = o;
            }
        }
    }
}

// out[b*NDIM+n] = sum over SPLITK partials (fully coalesced float4)
__global__ void asl_combine_kernel(float* __restrict__ out) {
    const int i = blockIdx.x * blockDim.x + threadIdx.x;   // float4 index
    const int total4 = BSZ * NDIM / 4;                     // 22016
    if (i < total4) {
        const float4* p4 = reinterpret_cast<const float4*>(g_partial);
        float4 a0 = p4[i];
        float4 a1 = p4[i +     total4];
        float4 a2 = p4[i + 2 * total4];
        float4 a3 = p4[i + 3 * total4];
        float4 o;
        o.x = (a0.x + a1.x) + (a2.x + a3.x);
        o.y = (a0.y + a1.y) + (a2.y + a3.y);
        o.z = (a0.z + a1.z) + (a2.z + a3.z);
        o.w = (a0.w + a1.w) + (a2.w + a3.w);
        reinterpret_cast<float4*>(out)[i] = o;
    }
}

extern "C" void kernel_launch(void* const* d_in, const int* in_sizes, int n_in,
                              void* d_out, int out_size) {
    const float* x = (const float*)d_in[0];
    const float* w = (const float*)d_in[1];
    if (n_in >= 2 && in_sizes[0] == NDIM * KDIM) {   // defensive order fix
        const float* t = x; x = w; w = t;
    }
    float* out = (float*)d_out;

    cudaFuncSetAttribute(asl_gemv_kernel,
                         cudaFuncAttributeMaxDynamicSharedMemorySize,
                         SMEM_BYTES);

    asl_gemv_kernel<<<NCTAS, THREADS, SMEM_BYTES>>>(x, w);

    const int total4 = BSZ * NDIM / 4;
    asl_combine_kernel<<<(total4 + 255) / 256, 256>>>(out);
}